// round 2
// baseline (speedup 1.0000x reference)
#include <cuda_runtime.h>
#include <math.h>

#define D   128
#define S   8
#define BB  16
#define NFR 16
#define NN  1024
#define EPSA 1e-8f
#define SCL 0.08838834764831845f  /* 128^-0.5 */

// ---------------- device scratch (no allocation allowed) ----------------
__device__ float g_slots[BB*S*D];       // current slots
__device__ float g_qt[BB*S*D];          // q @ Wk
__device__ float g_qb[BB*S];            // q . bk
__device__ float g_rowsum[BB*S];        // sum_j attn_ori
__device__ float g_upre[BB*S*D];        // attn @ LN(x)
__device__ float g_attn_warm[BB*S*NN];  // attn_ori scratch for warm-up iter
__device__ float g_stats[BB*NN*2];      // per-(b,j) mean,rstd for current frame

__device__ __forceinline__ float wred(float v){
    #pragma unroll
    for (int o = 16; o > 0; o >>= 1) v += __shfl_xor_sync(0xffffffffu, v, o);
    return v;
}

// ---------------- init: broadcast slots_init ----------------
__global__ void k_init(const float* __restrict__ slots_init){
    int i = blockIdx.x * blockDim.x + threadIdx.x;
    if (i < BB*S*D) g_slots[i] = slots_init[i & (S*D - 1)];
}

// ---------------- K1: qt = (LN(slots)@Wq^T + bq) @ Wk ; zero accumulators ----------------
__global__ void k_qt(const float* __restrict__ Wq, const float* __restrict__ bq,
                     const float* __restrict__ Wk, const float* __restrict__ bk,
                     const float* __restrict__ g_sl, const float* __restrict__ be_sl){
    int row = blockIdx.x;        // 0..127  (b*8+s)
    int t   = threadIdx.x;       // 0..127
    __shared__ float sv[D], q[D];
    __shared__ float red[4];

    float x = g_slots[row*D + t];
    float ws = wred(x);
    if ((t & 31) == 0) red[t >> 5] = ws;
    __syncthreads();
    float mean = (red[0]+red[1]+red[2]+red[3]) * (1.0f/D);
    __syncthreads();
    float dv = x - mean;
    ws = wred(dv*dv);
    if ((t & 31) == 0) red[t >> 5] = ws;
    __syncthreads();
    float var  = (red[0]+red[1]+red[2]+red[3]) * (1.0f/D);
    float rstd = rsqrtf(var + 1e-5f);
    sv[t] = dv * rstd * g_sl[t] + be_sl[t];
    __syncthreads();

    float acc = bq[t];
    #pragma unroll 8
    for (int e = 0; e < D; e++) acc += sv[e] * Wq[t*D + e];
    q[t] = acc;
    __syncthreads();

    // qt[e] = sum_d q[d] * Wk[d,e]   (coalesced over t=e)
    float acc2 = 0.0f;
    #pragma unroll 8
    for (int d = 0; d < D; d++) acc2 += q[d] * Wk[d*D + t];
    g_qt[row*D + t] = acc2;

    // qb = q . bk (bias of k projection)
    float ws2 = wred(q[t]*bk[t]);
    if ((t & 31) == 0) red[t >> 5] = ws2;
    __syncthreads();
    if (t == 0) g_qb[row] = red[0]+red[1]+red[2]+red[3];

    // zero accumulators for this iteration
    g_upre[row*D + t] = 0.0f;
    if (row == 0 && t < BB*S) g_rowsum[t] = 0.0f;
}

// ---------------- K2: attn_ori + rowsums + LN stats ----------------
// grid 512 (= 16 b * 32 chunks of 32 j), block 256 (8 warps, warp = 4 j)
__global__ void k_attn(const float* __restrict__ x, int f,
                       const float* __restrict__ g_in, const float* __restrict__ be_in,
                       float* __restrict__ out_attn, int warm){
    int b     = blockIdx.x >> 5;
    int chunk = blockIdx.x & 31;
    int t = threadIdx.x, w = t >> 5, lane = t & 31;

    __shared__ float qts[S*D];
    __shared__ float qbs[S];
    __shared__ float sums[S];
    __shared__ float sg[D], sb[D];

    for (int i = t; i < S*D; i += 256) qts[i] = g_qt[b*S*D + i];
    if (t < D)  { sg[t] = g_in[t]; sb[t] = be_in[t]; }
    if (t < S)  { qbs[t] = g_qb[b*S + t]; sums[t] = 0.0f; }
    __syncthreads();

    const float* xb = x + ((size_t)(b*NFR + f) * NN) * D;
    float* ao   = warm ? g_attn_warm : out_attn;
    size_t base = warm ? (size_t)b * (S*NN)
                       : ((size_t)(b*NFR + f)) * (S*NN);

    for (int it = 0; it < 4; it++) {
        int j = chunk*32 + w*4 + it;
        float4 xv = *(const float4*)(xb + (size_t)j*D + lane*4);
        float sm = wred(xv.x + xv.y + xv.z + xv.w);
        float mean = sm * (1.0f/D);
        float d0 = xv.x-mean, d1 = xv.y-mean, d2 = xv.z-mean, d3 = xv.w-mean;
        float vs = wred(d0*d0 + d1*d1 + d2*d2 + d3*d3);
        float rstd = rsqrtf(vs * (1.0f/D) + 1e-5f);
        if (lane == 0) {
            g_stats[(b*NN + j)*2 + 0] = mean;
            g_stats[(b*NN + j)*2 + 1] = rstd;
        }
        int e0 = lane*4;
        float l0 = d0*rstd*sg[e0+0] + sb[e0+0];
        float l1 = d1*rstd*sg[e0+1] + sb[e0+1];
        float l2 = d2*rstd*sg[e0+2] + sb[e0+2];
        float l3 = d3*rstd*sg[e0+3] + sb[e0+3];

        float dots[S];
        #pragma unroll
        for (int s = 0; s < S; s++) {
            const float* qr = &qts[s*D + e0];
            float p = l0*qr[0] + l1*qr[1] + l2*qr[2] + l3*qr[3];
            p = wred(p);
            dots[s] = (p + qbs[s]) * SCL;
        }
        // softmax over slots (all lanes redundantly)
        float mx = dots[0];
        #pragma unroll
        for (int s = 1; s < S; s++) mx = fmaxf(mx, dots[s]);
        float ssum = 0.0f;
        #pragma unroll
        for (int s = 0; s < S; s++) { dots[s] = __expf(dots[s] - mx); ssum += dots[s]; }
        float inv = 1.0f / ssum;
        #pragma unroll
        for (int s = 0; s < S; s++) {
            float p = dots[s] * inv + EPSA;
            if (lane == s) {
                ao[base + (size_t)s*NN + j] = p;
                atomicAdd(&sums[s], p);
            }
        }
    }
    __syncthreads();
    if (t < S) atomicAdd(&g_rowsum[b*S + t], sums[t]);
}

// ---------------- K3: updates_pre = (attn_ori/rowsum) @ LN(x) ----------------
// grid 128 (= 16 b * 8 j-chunks of 128), block 256 (e = t&127, slot-half = t>>7)
__global__ void k_upd(const float* __restrict__ x, int f,
                      const float* __restrict__ g_in, const float* __restrict__ be_in,
                      const float* __restrict__ out_attn, int warm){
    int b  = blockIdx.x >> 3;
    int jc = blockIdx.x & 7;
    int t = threadIdx.x;
    int e = t & 127, sh = t >> 7;

    float ge = g_in[e], bee = be_in[e];
    const float* xb = x + ((size_t)(b*NFR + f) * NN) * D;
    const float* ab = (warm ? g_attn_warm + (size_t)b*(S*NN)
                            : out_attn + ((size_t)(b*NFR + f))*(S*NN))
                      + (size_t)(sh*4)*NN;
    const float* st = &g_stats[b*NN*2];

    float a0 = 0.f, a1 = 0.f, a2 = 0.f, a3 = 0.f;
    int j0 = jc*128;
    for (int jj = 0; jj < 128; jj++) {
        int j = j0 + jj;
        float xv   = __ldg(xb + (size_t)j*D + e);
        float mean = __ldg(st + j*2 + 0);
        float rstd = __ldg(st + j*2 + 1);
        float ln = (xv - mean) * rstd * ge + bee;
        a0 += __ldg(ab + 0*NN + j) * ln;
        a1 += __ldg(ab + 1*NN + j) * ln;
        a2 += __ldg(ab + 2*NN + j) * ln;
        a3 += __ldg(ab + 3*NN + j) * ln;
    }
    int srow = b*S + sh*4;
    float r0 = g_rowsum[srow+0], r1 = g_rowsum[srow+1];
    float r2 = g_rowsum[srow+2], r3 = g_rowsum[srow+3];
    float* up = &g_upre[srow*D + e];
    atomicAdd(up + 0*D, a0 / r0);
    atomicAdd(up + 1*D, a1 / r1);
    atomicAdd(up + 2*D, a2 / r2);
    atomicAdd(up + 3*D, a3 / r3);
}

// ---------------- K4: updates@Wv^T+bv -> GRU -> LN -> FF -> slots(+out) ----------------
// grid 64 (2 rows per block), block 256 (d = t&127, rr = t>>7)
__global__ void k_gru(const float* __restrict__ Wv,  const float* __restrict__ bv,
                      const float* __restrict__ Wih, const float* __restrict__ Whh,
                      const float* __restrict__ bih, const float* __restrict__ bhh,
                      const float* __restrict__ gff, const float* __restrict__ beff,
                      const float* __restrict__ W1,  const float* __restrict__ b1,
                      const float* __restrict__ W2,  const float* __restrict__ b2,
                      float* __restrict__ out_slots, int f, int store){
    int t = threadIdx.x;
    int d = t & 127, rr = t >> 7;
    int row = blockIdx.x*2 + rr;

    __shared__ float us[2][D], hs[2][D], lv[2][D], tt[2][D];
    __shared__ float red[8], red2[8];

    us[rr][d] = g_upre[row*D + d];
    hs[rr][d] = g_slots[row*D + d];
    __syncthreads();

    // updates = upre @ Wv^T + bv
    float u = bv[d];
    #pragma unroll 4
    for (int e = 0; e < D; e++) u += us[rr][e] * Wv[d*D + e];
    __syncthreads();
    us[rr][d] = u;
    __syncthreads();

    // GRU cell
    float gir = bih[d], giz = bih[d+D], ginn = bih[d+2*D];
    float ghr = bhh[d], ghz = bhh[d+D], ghn  = bhh[d+2*D];
    #pragma unroll 2
    for (int e = 0; e < D; e++) {
        float uu = us[rr][e], hh = hs[rr][e];
        gir  += uu * Wih[(d      )*D + e];
        giz  += uu * Wih[(d +   D)*D + e];
        ginn += uu * Wih[(d + 2*D)*D + e];
        ghr  += hh * Whh[(d      )*D + e];
        ghz  += hh * Whh[(d +   D)*D + e];
        ghn  += hh * Whh[(d + 2*D)*D + e];
    }
    float r = 1.0f / (1.0f + __expf(-(gir + ghr)));
    float z = 1.0f / (1.0f + __expf(-(giz + ghz)));
    float n = tanhf(ginn + r * ghn);
    float hv = (1.0f - z) * n + z * hs[rr][d];

    // LN(hv) per row (4 warps per row: warps 0-3 -> rr=0, 4-7 -> rr=1)
    float ws = wred(hv);
    if ((t & 31) == 0) red[t >> 5] = ws;
    __syncthreads();
    float mean = (red[rr*4+0]+red[rr*4+1]+red[rr*4+2]+red[rr*4+3]) * (1.0f/D);
    float dv = hv - mean;
    ws = wred(dv*dv);
    if ((t & 31) == 0) red2[t >> 5] = ws;
    __syncthreads();
    float var  = (red2[rr*4+0]+red2[rr*4+1]+red2[rr*4+2]+red2[rr*4+3]) * (1.0f/D);
    float rstd = rsqrtf(var + 1e-5f);
    lv[rr][d] = dv * rstd * gff[d] + beff[d];
    __syncthreads();

    float tv = b1[d];
    #pragma unroll 4
    for (int e = 0; e < D; e++) tv += lv[rr][e] * W1[d*D + e];
    tt[rr][d] = fmaxf(tv, 0.0f);
    __syncthreads();

    float ff = b2[d];
    #pragma unroll 4
    for (int h = 0; h < D; h++) ff += tt[rr][h] * W2[d*D + h];
    float outv = hv + ff;

    g_slots[row*D + d] = outv;
    if (store) {
        int b = row >> 3, s = row & 7;
        out_slots[(((size_t)b*NFR + f)*S + s)*D + d] = outv;
    }
}

// ---------------- host ----------------
extern "C" void kernel_launch(void* const* d_in, const int* in_sizes, int n_in,
                              void* d_out, int out_size){
    const float* inputs     = (const float*)d_in[0];
    const float* slots_init = (const float*)d_in[1];
    const float* Wq  = (const float*)d_in[2];
    const float* bq  = (const float*)d_in[3];
    const float* Wk  = (const float*)d_in[4];
    const float* bk  = (const float*)d_in[5];
    const float* Wv  = (const float*)d_in[6];
    const float* bv  = (const float*)d_in[7];
    const float* W1  = (const float*)d_in[8];
    const float* b1  = (const float*)d_in[9];
    const float* W2  = (const float*)d_in[10];
    const float* b2  = (const float*)d_in[11];
    const float* Wih = (const float*)d_in[12];
    const float* Whh = (const float*)d_in[13];
    const float* bih = (const float*)d_in[14];
    const float* bhh = (const float*)d_in[15];
    const float* g_in  = (const float*)d_in[16];
    const float* be_in = (const float*)d_in[17];
    const float* g_sl  = (const float*)d_in[18];
    const float* be_sl = (const float*)d_in[19];
    const float* g_ff  = (const float*)d_in[20];
    const float* be_ff = (const float*)d_in[21];

    float* out       = (float*)d_out;
    float* out_slots = out;                         // [B, NF, S, D]
    float* out_attn  = out + (size_t)BB*NFR*S*D;    // [B, NF, S, N]

    k_init<<<64, 256>>>(slots_init);

    for (int it = 0; it < NFR + 1; ++it) {
        int f    = (it == 0) ? 0 : it - 1;
        int warm = (it == 0) ? 1 : 0;
        k_qt  <<<128, 128>>>(Wq, bq, Wk, bk, g_sl, be_sl);
        k_attn<<<512, 256>>>(inputs, f, g_in, be_in, out_attn, warm);
        k_upd <<<128, 256>>>(inputs, f, g_in, be_in, out_attn, warm);
        k_gru <<<64, 256>>>(Wv, bv, Wih, Whh, bih, bhh, g_ff, be_ff,
                            W1, b1, W2, b2, out_slots, f, warm ? 0 : 1);
    }
}

// round 7
// speedup vs baseline: 3.8782x; 3.8782x over previous
#include <cuda_runtime.h>
#include <math.h>

#define D   128
#define S   8
#define BB  16
#define NFR 16
#define NN  1024
#define EPSA 1e-8f
#define SCL 0.08838834764831845f  /* 128^-0.5 */

// ---------------- device scratch ----------------
__device__ float g_slots[BB*S*D];       // current slots
__device__ float g_qt[BB*S*D];          // q @ Wk
__device__ float g_qb[BB*S];            // q . bk
__device__ float g_rowsum[BB*S];        // sum_j attn_ori
__device__ float g_upre[BB*S*D];        // sum_j attn_ori * LN(x)  (unnormalized)
__device__ float g_attn_warm[BB*S*NN];  // attn scratch for warm-up iter

__device__ __forceinline__ float wred(float v){
    #pragma unroll
    for (int o = 16; o > 0; o >>= 1) v += __shfl_xor_sync(0xffffffffu, v, o);
    return v;
}

// ---------------- init ----------------
__global__ void k_init(const float* __restrict__ slots_init){
    int i = blockIdx.x * blockDim.x + threadIdx.x;
    if (i < BB*S*D) g_slots[i] = slots_init[i & (S*D - 1)];
}

// ---------------- K_qt0: standalone q-projection (only before first iter) ----------------
__global__ void k_qt0(const float* __restrict__ Wq, const float* __restrict__ bq,
                      const float* __restrict__ Wk, const float* __restrict__ bk,
                      const float* __restrict__ g_sl, const float* __restrict__ be_sl){
    int row = blockIdx.x;        // 0..127
    int t   = threadIdx.x;       // 0..127
    __shared__ float sv[D], q[D];
    __shared__ float red[4];

    float x = g_slots[row*D + t];
    float ws = wred(x);
    if ((t & 31) == 0) red[t >> 5] = ws;
    __syncthreads();
    float mean = (red[0]+red[1]+red[2]+red[3]) * (1.0f/D);
    __syncthreads();
    float dv = x - mean;
    ws = wred(dv*dv);
    if ((t & 31) == 0) red[t >> 5] = ws;
    __syncthreads();
    float var  = (red[0]+red[1]+red[2]+red[3]) * (1.0f/D);
    float rstd = rsqrtf(var + 1e-5f);
    sv[t] = dv * rstd * g_sl[t] + be_sl[t];
    __syncthreads();

    float acc = bq[t];
    #pragma unroll 8
    for (int e = 0; e < D; e++) acc += sv[e] * Wq[t*D + e];
    q[t] = acc;
    __syncthreads();

    float acc2 = 0.0f;
    #pragma unroll 8
    for (int d = 0; d < D; d++) acc2 += q[d] * Wk[d*D + t];
    g_qt[row*D + t] = acc2;

    float ws2 = wred(q[t]*bk[t]);
    if ((t & 31) == 0) red[t >> 5] = ws2;
    __syncthreads();
    if (t == 0) g_qb[row] = red[0]+red[1]+red[2]+red[3];

    g_upre[row*D + t] = 0.0f;
    if (row == 0 && t < BB*S) g_rowsum[t] = 0.0f;
}

// ---------------- K_attn_f: attn + rowsums + fused (attn @ LN(x)) accumulation ----------------
// grid 512 (= 16 b * 32 chunks of 32 j), block 256 (8 warps, warp = 4 j)
__global__ void k_attn_f(const float* __restrict__ x, int f,
                         const float* __restrict__ g_in, const float* __restrict__ be_in,
                         float* __restrict__ out_attn, int warm){
    int b     = blockIdx.x >> 5;
    int chunk = blockIdx.x & 31;
    int t = threadIdx.x, w = t >> 5, lane = t & 31;

    __shared__ float qts[S*D];
    __shared__ float qbs[S];
    __shared__ float sg[D], sb[D];
    __shared__ float swacc[8*S*4*32];   // [warp][slot][q][lane]  32KB

    for (int i = t; i < S*D; i += 256) qts[i] = g_qt[b*S*D + i];
    if (t < D)  { sg[t] = g_in[t]; sb[t] = be_in[t]; }
    if (t < S)  { qbs[t] = g_qb[b*S + t]; }
    __syncthreads();

    const float* xb = x + ((size_t)(b*NFR + f) * NN) * D;
    float* ao   = warm ? g_attn_warm : out_attn;
    size_t base = warm ? (size_t)b * (S*NN)
                       : ((size_t)(b*NFR + f)) * (S*NN);

    int e0 = lane*4;
    float w0 = sg[e0], w1 = sg[e0+1], w2 = sg[e0+2], w3 = sg[e0+3];
    float c0 = sb[e0], c1 = sb[e0+1], c2 = sb[e0+2], c3 = sb[e0+3];

    int jbase = chunk*32 + w*4;
    float4 xv4[4];
    #pragma unroll
    for (int it = 0; it < 4; it++)
        xv4[it] = *(const float4*)(xb + (size_t)(jbase + it)*D + e0);

    float acc[32];
    #pragma unroll
    for (int i = 0; i < 32; i++) acc[i] = 0.0f;
    float rsl = 0.0f;

    #pragma unroll
    for (int it = 0; it < 4; it++) {
        int j = jbase + it;
        float4 xv = xv4[it];
        float sm = wred(xv.x + xv.y + xv.z + xv.w);
        float mean = sm * (1.0f/D);
        float d0 = xv.x-mean, d1 = xv.y-mean, d2 = xv.z-mean, d3 = xv.w-mean;
        float vs = wred(d0*d0 + d1*d1 + d2*d2 + d3*d3);
        float rstd = rsqrtf(vs * (1.0f/D) + 1e-5f);
        float l0 = d0*rstd*w0 + c0;
        float l1 = d1*rstd*w1 + c1;
        float l2 = d2*rstd*w2 + c2;
        float l3 = d3*rstd*w3 + c3;

        float dots[S];
        #pragma unroll
        for (int s = 0; s < S; s++) {
            const float* qr = &qts[s*D + e0];
            float p = l0*qr[0] + l1*qr[1] + l2*qr[2] + l3*qr[3];
            p = wred(p);
            dots[s] = (p + qbs[s]) * SCL;
        }
        float mx = dots[0];
        #pragma unroll
        for (int s = 1; s < S; s++) mx = fmaxf(mx, dots[s]);
        float ssum = 0.0f;
        #pragma unroll
        for (int s = 0; s < S; s++) { dots[s] = __expf(dots[s] - mx); ssum += dots[s]; }
        float inv = 1.0f / ssum;
        #pragma unroll
        for (int s = 0; s < S; s++) {
            float p = dots[s] * inv + EPSA;
            if (lane == s) {
                ao[base + (size_t)s*NN + j] = p;
                rsl += p;
            }
            acc[s*4+0] += p * l0;
            acc[s*4+1] += p * l1;
            acc[s*4+2] += p * l2;
            acc[s*4+3] += p * l3;
        }
    }

    if (lane < S) atomicAdd(&g_rowsum[b*S + lane], rsl);

    #pragma unroll
    for (int s = 0; s < S; s++)
        #pragma unroll
        for (int q = 0; q < 4; q++)
            swacc[((w*S + s)*4 + q)*32 + lane] = acc[s*4+q];
    __syncthreads();

    for (int i = t; i < S*D; i += 256) {
        int s = i >> 7, rem = i & 127, q = rem >> 5, l2 = rem & 31;
        float v = 0.0f;
        #pragma unroll
        for (int ww = 0; ww < 8; ww++) v += swacc[((ww*S + s)*4 + q)*32 + l2];
        int e = l2*4 + q;
        atomicAdd(&g_upre[(b*S + s)*D + e], v);
    }
}

// ---------------- K_gru_f: Wv -> GRU -> LN -> FF -> slots, then next-iter q/qt ----------------
// grid 32, block 128: each thread handles dim t for 4 consecutive slot-rows
__global__ void k_gru_f(const float* __restrict__ Wv,  const float* __restrict__ bv,
                        const float* __restrict__ Wih, const float* __restrict__ Whh,
                        const float* __restrict__ bih, const float* __restrict__ bhh,
                        const float* __restrict__ gff, const float* __restrict__ beff,
                        const float* __restrict__ W1,  const float* __restrict__ b1,
                        const float* __restrict__ W2,  const float* __restrict__ b2,
                        const float* __restrict__ Wq,  const float* __restrict__ bq,
                        const float* __restrict__ Wk,  const float* __restrict__ bk,
                        const float* __restrict__ g_sl, const float* __restrict__ be_sl,
                        float* __restrict__ out_slots, int f, int store){
    int t = threadIdx.x;            // 0..127
    int w = t >> 5, lane = t & 31;
    int row0 = blockIdx.x * 4;

    __shared__ float us[4][D], hs[4][D], lv[4][D], tt[4][D], qs[4][D];
    __shared__ float redm[4][4], redv[4][4];

    #pragma unroll
    for (int r = 0; r < 4; r++) {
        int row = row0 + r;
        us[r][t] = g_upre[row*D + t] / g_rowsum[row];
        hs[r][t] = g_slots[row*D + t];
        g_upre[row*D + t] = 0.0f;   // reset for next iteration
    }
    if (t < 4) g_rowsum[row0 + t] = 0.0f;
    __syncthreads();

    // u = us @ Wv^T + bv
    float u[4];
    #pragma unroll
    for (int r = 0; r < 4; r++) u[r] = bv[t];
    {
        const float4* Wv4 = (const float4*)(Wv + t*D);
        #pragma unroll 4
        for (int e4 = 0; e4 < 32; e4++) {
            float4 wv = Wv4[e4];
            #pragma unroll
            for (int r = 0; r < 4; r++) {
                float4 uv = ((const float4*)us[r])[e4];
                u[r] += uv.x*wv.x + uv.y*wv.y + uv.z*wv.z + uv.w*wv.w;
            }
        }
    }
    __syncthreads();
    #pragma unroll
    for (int r = 0; r < 4; r++) us[r][t] = u[r];
    __syncthreads();

    // GRU gates
    float gir[4], giz[4], gin[4], ghr[4], ghz[4], ghn[4];
    #pragma unroll
    for (int r = 0; r < 4; r++) {
        gir[r] = bih[t]; giz[r] = bih[t+D]; gin[r] = bih[t+2*D];
        ghr[r] = bhh[t]; ghz[r] = bhh[t+D]; ghn[r] = bhh[t+2*D];
    }
    {
        const float4* Ar = (const float4*)(Wih + (t      )*D);
        const float4* Az = (const float4*)(Wih + (t +   D)*D);
        const float4* An = (const float4*)(Wih + (t + 2*D)*D);
        const float4* Br = (const float4*)(Whh + (t      )*D);
        const float4* Bz = (const float4*)(Whh + (t +   D)*D);
        const float4* Bn = (const float4*)(Whh + (t + 2*D)*D);
        #pragma unroll 2
        for (int e4 = 0; e4 < 32; e4++) {
            float4 ar = Ar[e4], az = Az[e4], an = An[e4];
            float4 br = Br[e4], bz = Bz[e4], bn = Bn[e4];
            #pragma unroll
            for (int r = 0; r < 4; r++) {
                float4 uu = ((const float4*)us[r])[e4];
                float4 hh = ((const float4*)hs[r])[e4];
                gir[r] += uu.x*ar.x + uu.y*ar.y + uu.z*ar.z + uu.w*ar.w;
                giz[r] += uu.x*az.x + uu.y*az.y + uu.z*az.z + uu.w*az.w;
                gin[r] += uu.x*an.x + uu.y*an.y + uu.z*an.z + uu.w*an.w;
                ghr[r] += hh.x*br.x + hh.y*br.y + hh.z*br.z + hh.w*br.w;
                ghz[r] += hh.x*bz.x + hh.y*bz.y + hh.z*bz.z + hh.w*bz.w;
                ghn[r] += hh.x*bn.x + hh.y*bn.y + hh.z*bn.z + hh.w*bn.w;
            }
        }
    }
    float hv[4];
    #pragma unroll
    for (int r = 0; r < 4; r++) {
        float rg = 1.0f / (1.0f + __expf(-(gir[r] + ghr[r])));
        float zg = 1.0f / (1.0f + __expf(-(giz[r] + ghz[r])));
        float ng = tanhf(gin[r] + rg * ghn[r]);
        hv[r] = (1.0f - zg) * ng + zg * hs[r][t];
    }

    // LN(hv) with gff/beff
    #pragma unroll
    for (int r = 0; r < 4; r++) {
        float s1 = wred(hv[r]);
        if (lane == 0) redm[r][w] = s1;
    }
    __syncthreads();
    float mn[4];
    #pragma unroll
    for (int r = 0; r < 4; r++) {
        mn[r] = (redm[r][0]+redm[r][1]+redm[r][2]+redm[r][3]) * (1.0f/D);
        float dv = hv[r] - mn[r];
        float s2 = wred(dv*dv);
        if (lane == 0) redv[r][w] = s2;
    }
    __syncthreads();
    #pragma unroll
    for (int r = 0; r < 4; r++) {
        float var  = (redv[r][0]+redv[r][1]+redv[r][2]+redv[r][3]) * (1.0f/D);
        float rstd = rsqrtf(var + 1e-5f);
        lv[r][t] = (hv[r] - mn[r]) * rstd * gff[t] + beff[t];
    }
    __syncthreads();

    // FF: relu(lv @ W1^T + b1) @ W2^T + b2
    float tv[4];
    #pragma unroll
    for (int r = 0; r < 4; r++) tv[r] = b1[t];
    {
        const float4* W14 = (const float4*)(W1 + t*D);
        #pragma unroll 4
        for (int e4 = 0; e4 < 32; e4++) {
            float4 wv = W14[e4];
            #pragma unroll
            for (int r = 0; r < 4; r++) {
                float4 lvv = ((const float4*)lv[r])[e4];
                tv[r] += lvv.x*wv.x + lvv.y*wv.y + lvv.z*wv.z + lvv.w*wv.w;
            }
        }
    }
    #pragma unroll
    for (int r = 0; r < 4; r++) tt[r][t] = fmaxf(tv[r], 0.0f);
    __syncthreads();

    float outv[4];
    {
        const float4* W24 = (const float4*)(W2 + t*D);
        float ff[4];
        #pragma unroll
        for (int r = 0; r < 4; r++) ff[r] = b2[t];
        #pragma unroll 4
        for (int h4 = 0; h4 < 32; h4++) {
            float4 wv = W24[h4];
            #pragma unroll
            for (int r = 0; r < 4; r++) {
                float4 tvv = ((const float4*)tt[r])[h4];
                ff[r] += tvv.x*wv.x + tvv.y*wv.y + tvv.z*wv.z + tvv.w*wv.w;
            }
        }
        #pragma unroll
        for (int r = 0; r < 4; r++) outv[r] = hv[r] + ff[r];
    }

    #pragma unroll
    for (int r = 0; r < 4; r++) {
        int row = row0 + r;
        g_slots[row*D + t] = outv[r];
        if (store) {
            int b = row >> 3, s = row & 7;
            out_slots[(((size_t)b*NFR + f)*S + s)*D + t] = outv[r];
        }
    }

    // ---- fused q / qt projection for NEXT iteration ----
    __syncthreads();
    #pragma unroll
    for (int r = 0; r < 4; r++) {
        float s1 = wred(outv[r]);
        if (lane == 0) redm[r][w] = s1;
    }
    __syncthreads();
    #pragma unroll
    for (int r = 0; r < 4; r++) {
        mn[r] = (redm[r][0]+redm[r][1]+redm[r][2]+redm[r][3]) * (1.0f/D);
        float dv = outv[r] - mn[r];
        float s2 = wred(dv*dv);
        if (lane == 0) redv[r][w] = s2;
    }
    __syncthreads();
    #pragma unroll
    for (int r = 0; r < 4; r++) {
        float var  = (redv[r][0]+redv[r][1]+redv[r][2]+redv[r][3]) * (1.0f/D);
        float rstd = rsqrtf(var + 1e-5f);
        lv[r][t] = (outv[r] - mn[r]) * rstd * g_sl[t] + be_sl[t];  // reuse lv as sv
    }
    __syncthreads();

    float q[4];
    #pragma unroll
    for (int r = 0; r < 4; r++) q[r] = bq[t];
    {
        const float4* Wq4 = (const float4*)(Wq + t*D);
        #pragma unroll 4
        for (int e4 = 0; e4 < 32; e4++) {
            float4 wv = Wq4[e4];
            #pragma unroll
            for (int r = 0; r < 4; r++) {
                float4 sv = ((const float4*)lv[r])[e4];
                q[r] += sv.x*wv.x + sv.y*wv.y + sv.z*wv.z + sv.w*wv.w;
            }
        }
    }
    float bkt = bk[t];
    #pragma unroll
    for (int r = 0; r < 4; r++) {
        qs[r][t] = q[r];
        float s1 = wred(q[r] * bkt);
        if (lane == 0) redm[r][w] = s1;
    }
    __syncthreads();
    if (t < 4) g_qb[row0 + t] = redm[t][0]+redm[t][1]+redm[t][2]+redm[t][3];

    // qt[r][e] = sum_d qs[r][d] * Wk[d,e]   (thread t = e, coalesced over d rows)
    float qt[4] = {0.f, 0.f, 0.f, 0.f};
    #pragma unroll 4
    for (int d = 0; d < D; d++) {
        float wk = Wk[d*D + t];
        #pragma unroll
        for (int r = 0; r < 4; r++) qt[r] += qs[r][d] * wk;
    }
    #pragma unroll
    for (int r = 0; r < 4; r++) g_qt[(row0 + r)*D + t] = qt[r];
}

// ---------------- host ----------------
extern "C" void kernel_launch(void* const* d_in, const int* in_sizes, int n_in,
                              void* d_out, int out_size){
    const float* inputs     = (const float*)d_in[0];
    const float* slots_init = (const float*)d_in[1];
    const float* Wq  = (const float*)d_in[2];
    const float* bq  = (const float*)d_in[3];
    const float* Wk  = (const float*)d_in[4];
    const float* bk  = (const float*)d_in[5];
    const float* Wv  = (const float*)d_in[6];
    const float* bv  = (const float*)d_in[7];
    const float* W1  = (const float*)d_in[8];
    const float* b1  = (const float*)d_in[9];
    const float* W2  = (const float*)d_in[10];
    const float* b2  = (const float*)d_in[11];
    const float* Wih = (const float*)d_in[12];
    const float* Whh = (const float*)d_in[13];
    const float* bih = (const float*)d_in[14];
    const float* bhh = (const float*)d_in[15];
    const float* g_in  = (const float*)d_in[16];
    const float* be_in = (const float*)d_in[17];
    const float* g_sl  = (const float*)d_in[18];
    const float* be_sl = (const float*)d_in[19];
    const float* g_ff  = (const float*)d_in[20];
    const float* be_ff = (const float*)d_in[21];

    float* out       = (float*)d_out;
    float* out_slots = out;                         // [B, NF, S, D]
    float* out_attn  = out + (size_t)BB*NFR*S*D;    // [B, NF, S, N]

    k_init<<<64, 256>>>(slots_init);
    k_qt0 <<<128, 128>>>(Wq, bq, Wk, bk, g_sl, be_sl);

    for (int it = 0; it < NFR + 1; ++it) {
        int f    = (it == 0) ? 0 : it - 1;
        int warm = (it == 0) ? 1 : 0;
        k_attn_f<<<512, 256>>>(inputs, f, g_in, be_in, out_attn, warm);
        k_gru_f <<<32, 128>>>(Wv, bv, Wih, Whh, bih, bhh, g_ff, be_ff,
                              W1, b1, W2, b2, Wq, bq, Wk, bk, g_sl, be_sl,
                              out_slots, f, warm ? 0 : 1);
    }
}

// round 10
// speedup vs baseline: 4.6886x; 1.2090x over previous
#include <cuda_runtime.h>
#include <math.h>

#define D    128
#define S    8
#define BB   16
#define NFR  16
#define NN   1024
#define EPSA 1e-8f
#define SCL  0.08838834764831845f  /* 128^-0.5 */
#define NBLK 128
#define THR  256

// ---------------- device scratch ----------------
__device__ float g_slots[BB*S*D];
__device__ float g_qt[BB*S*D];
__device__ float g_qb[BB*S];
__device__ float g_upart[BB*8*S*D];     // per-(b,jc) partial of attn @ LN(x)
__device__ float g_rspart[BB*8*S];      // per-(b,jc) partial rowsums
__device__ float g_attn_warm[BB*S*NN];  // warm-up attn scratch
__device__ unsigned g_bar_gen;
__device__ unsigned g_bar_cnt;

// ---------------- shared union ----------------
struct SA {
    float qts[S*D];
    float sg[D], sb[D];
    float qbs[S];
    float swacc[8*S*4*32];   // 32 KB
    float srs[8][8];
};
struct SG {
    float us[2][D], hs[2][D];
    float sgi[2][3][D], sgh[2][3][D];
    float part[4*D];         // flat: [(row*2 + half)*D + d]
    float bufA[2][D], bufB[2][D];
    float red[2][4], red2[2][4];
};
union SU { SA a; SG g; };

__device__ __forceinline__ float wred(float v){
    #pragma unroll
    for (int o = 16; o > 0; o >>= 1) v += __shfl_xor_sync(0xffffffffu, v, o);
    return v;
}

// ---------------- grid barrier (all NBLK blocks resident: single wave) ----------------
__device__ __forceinline__ void gbar(){
    __syncthreads();
    if (threadIdx.x == 0){
        volatile unsigned* vg = &g_bar_gen;
        __threadfence();                       // my writes visible before arrival
        unsigned gen = *vg;
        if (atomicAdd(&g_bar_cnt, 1u) == NBLK - 1u){
            g_bar_cnt = 0u;
            __threadfence();
            *vg = gen + 1u;
        } else {
            while (*vg == gen) { }
        }
        __threadfence();                       // invalidate stale L1 before reading others' data
    }
    __syncthreads();
}

// ---------------- helpers ----------------
// partial matvec: for both rows, partial dot over e-half h. W row-major [D][D].
// part layout: part[(row*2 + h)*D + d]
__device__ __forceinline__ void mv_part(const float* __restrict__ W,
                                        const float (*in)[D],
                                        float* part, int d, int h){
    const float4* Wr = (const float4*)(W + d*D) + h*16;
    const float4* i0 = ((const float4*)in[0]) + h*16;
    const float4* i1 = ((const float4*)in[1]) + h*16;
    float p0 = 0.f, p1 = 0.f;
    #pragma unroll
    for (int e4 = 0; e4 < 16; e4++){
        float4 wv = Wr[e4], a = i0[e4], b = i1[e4];
        p0 += a.x*wv.x + a.y*wv.y + a.z*wv.z + a.w*wv.w;
        p1 += b.x*wv.x + b.y*wv.y + b.z*wv.z + b.w*wv.w;
    }
    part[(0*2+h)*D + d] = p0;
    part[(1*2+h)*D + d] = p1;
}

// LayerNorm over a 128-dim row; 2 rows per block, row = h (warps 0-3 -> h=0, 4-7 -> h=1)
__device__ __forceinline__ float ln_rowpair(float v, int t, float* red, float* red2,
                                            const float* __restrict__ gamma,
                                            const float* __restrict__ beta,
                                            int d, int h){
    int w = t >> 5, lane = t & 31;
    float s1 = wred(v);
    if (lane == 0) red[h*4 + (w&3)] = s1;
    __syncthreads();
    float mean = (red[h*4+0]+red[h*4+1]+red[h*4+2]+red[h*4+3]) * (1.0f/D);
    float dv = v - mean;
    float s2 = wred(dv*dv);
    if (lane == 0) red2[h*4 + (w&3)] = s2;
    __syncthreads();
    float var = (red2[h*4+0]+red2[h*4+1]+red2[h*4+2]+red2[h*4+3]) * (1.0f/D);
    return dv * rsqrtf(var + 1e-5f) * gamma[d] + beta[d];
}

// ---------------- slot update phase: blocks 0..63, 2 rows each ----------------
__device__ void slot_update(SU* sm, int blk, int t, bool full,
    const float* __restrict__ Wv,  const float* __restrict__ bv,
    const float* __restrict__ Wih, const float* __restrict__ Whh,
    const float* __restrict__ bih, const float* __restrict__ bhh,
    const float* __restrict__ gff, const float* __restrict__ beff,
    const float* __restrict__ W1,  const float* __restrict__ b1,
    const float* __restrict__ W2,  const float* __restrict__ b2,
    const float* __restrict__ Wq,  const float* __restrict__ bq,
    const float* __restrict__ Wk,  const float* __restrict__ bk,
    const float* __restrict__ g_sl, const float* __restrict__ be_sl,
    float* __restrict__ out_slots, int f, int store)
{
    int d = t & 127, h = t >> 7, w = t >> 5, lane = t & 31;
    int row0 = blk * 2;
    int rowh = row0 + h;
    float outv;
    float* part = sm->g.part;

    if (full){
        int bh = rowh >> 3, sh = rowh & 7;
        float up = 0.f, rs = 0.f;
        #pragma unroll
        for (int jc = 0; jc < 8; jc++){
            up += g_upart[((bh*8 + jc)*S + sh)*D + d];
            rs += g_rspart[(bh*8 + jc)*S + sh];
        }
        sm->g.us[h][d] = up / rs;
        sm->g.hs[h][d] = g_slots[rowh*D + d];
        __syncthreads();

        // u = us @ Wv^T + bv
        mv_part(Wv, sm->g.us, part, d, h);
        __syncthreads();
        float uval = part[(h*2+0)*D + d] + part[(h*2+1)*D + d] + bv[d];
        __syncthreads();
        sm->g.us[h][d] = uval;
        __syncthreads();

        // GRU gates: half 0 computes gi (input side), half 1 computes gh (hidden side)
        if (h == 0){
            const float4* Wr = (const float4*)(Wih + (d      )*D);
            const float4* Wz = (const float4*)(Wih + (d +   D)*D);
            const float4* Wn = (const float4*)(Wih + (d + 2*D)*D);
            float r0=0,z0=0,n0=0, r1=0,z1=0,n1=0;
            #pragma unroll 4
            for (int e4 = 0; e4 < 32; e4++){
                float4 wr = Wr[e4], wz = Wz[e4], wn = Wn[e4];
                float4 u0 = ((const float4*)sm->g.us[0])[e4];
                float4 u1 = ((const float4*)sm->g.us[1])[e4];
                r0 += u0.x*wr.x + u0.y*wr.y + u0.z*wr.z + u0.w*wr.w;
                z0 += u0.x*wz.x + u0.y*wz.y + u0.z*wz.z + u0.w*wz.w;
                n0 += u0.x*wn.x + u0.y*wn.y + u0.z*wn.z + u0.w*wn.w;
                r1 += u1.x*wr.x + u1.y*wr.y + u1.z*wr.z + u1.w*wr.w;
                z1 += u1.x*wz.x + u1.y*wz.y + u1.z*wz.z + u1.w*wz.w;
                n1 += u1.x*wn.x + u1.y*wn.y + u1.z*wn.z + u1.w*wn.w;
            }
            sm->g.sgi[0][0][d]=r0; sm->g.sgi[0][1][d]=z0; sm->g.sgi[0][2][d]=n0;
            sm->g.sgi[1][0][d]=r1; sm->g.sgi[1][1][d]=z1; sm->g.sgi[1][2][d]=n1;
        } else {
            const float4* Wr = (const float4*)(Whh + (d      )*D);
            const float4* Wz = (const float4*)(Whh + (d +   D)*D);
            const float4* Wn = (const float4*)(Whh + (d + 2*D)*D);
            float r0=0,z0=0,n0=0, r1=0,z1=0,n1=0;
            #pragma unroll 4
            for (int e4 = 0; e4 < 32; e4++){
                float4 wr = Wr[e4], wz = Wz[e4], wn = Wn[e4];
                float4 h0 = ((const float4*)sm->g.hs[0])[e4];
                float4 h1 = ((const float4*)sm->g.hs[1])[e4];
                r0 += h0.x*wr.x + h0.y*wr.y + h0.z*wr.z + h0.w*wr.w;
                z0 += h0.x*wz.x + h0.y*wz.y + h0.z*wz.z + h0.w*wz.w;
                n0 += h0.x*wn.x + h0.y*wn.y + h0.z*wn.z + h0.w*wn.w;
                r1 += h1.x*wr.x + h1.y*wr.y + h1.z*wr.z + h1.w*wr.w;
                z1 += h1.x*wz.x + h1.y*wz.y + h1.z*wz.z + h1.w*wz.w;
                n1 += h1.x*wn.x + h1.y*wn.y + h1.z*wn.z + h1.w*wn.w;
            }
            sm->g.sgh[0][0][d]=r0; sm->g.sgh[0][1][d]=z0; sm->g.sgh[0][2][d]=n0;
            sm->g.sgh[1][0][d]=r1; sm->g.sgh[1][1][d]=z1; sm->g.sgh[1][2][d]=n1;
        }
        __syncthreads();

        float gir = sm->g.sgi[h][0][d] + bih[d];
        float giz = sm->g.sgi[h][1][d] + bih[d+D];
        float gin_= sm->g.sgi[h][2][d] + bih[d+2*D];
        float ghr = sm->g.sgh[h][0][d] + bhh[d];
        float ghz = sm->g.sgh[h][1][d] + bhh[d+D];
        float ghn = sm->g.sgh[h][2][d] + bhh[d+2*D];
        float rg = 1.0f / (1.0f + __expf(-(gir + ghr)));
        float zg = 1.0f / (1.0f + __expf(-(giz + ghz)));
        float ng = tanhf(gin_ + rg * ghn);
        float hv = (1.0f - zg) * ng + zg * sm->g.hs[h][d];

        // LN (gff/beff) -> FF
        float lvv = ln_rowpair(hv, t, &sm->g.red[0][0], &sm->g.red2[0][0], gff, beff, d, h);
        sm->g.bufA[h][d] = lvv;
        __syncthreads();

        mv_part(W1, sm->g.bufA, part, d, h);
        __syncthreads();
        float tv = fmaxf(part[(h*2+0)*D + d] + part[(h*2+1)*D + d] + b1[d], 0.0f);
        __syncthreads();
        sm->g.bufB[h][d] = tv;
        __syncthreads();

        mv_part(W2, sm->g.bufB, part, d, h);
        __syncthreads();
        outv = hv + part[(h*2+0)*D + d] + part[(h*2+1)*D + d] + b2[d];

        g_slots[rowh*D + d] = outv;
        if (store){
            int b = rowh >> 3, s = rowh & 7;
            out_slots[(((size_t)b*NFR + f)*S + s)*D + d] = outv;
        }
        __syncthreads();
    } else {
        outv = g_slots[rowh*D + d];
        __syncthreads();
    }

    // ---- q projection for next iteration ----
    float sv = ln_rowpair(outv, t, &sm->g.red[0][0], &sm->g.red2[0][0], g_sl, be_sl, d, h);
    sm->g.bufA[h][d] = sv;
    __syncthreads();
    mv_part(Wq, sm->g.bufA, part, d, h);
    __syncthreads();
    float qv = part[(h*2+0)*D + d] + part[(h*2+1)*D + d] + bq[d];
    __syncthreads();
    sm->g.bufB[h][d] = qv;
    // qb[row] = q . bk
    float s1 = wred(qv * bk[d]);
    if (lane == 0) sm->g.red[h][w & 3] = s1;
    __syncthreads();
    if (t < 2) g_qb[row0 + t] = sm->g.red[t][0]+sm->g.red[t][1]+sm->g.red[t][2]+sm->g.red[t][3];

    // qt[e] = sum_d q[d] * Wk[d,e]  (split d-sum over halves)
    {
        int e = d;
        float q0 = 0.f, q1 = 0.f;
        #pragma unroll 8
        for (int dd = h*64; dd < h*64 + 64; dd++){
            float wk = Wk[dd*D + e];
            q0 += sm->g.bufB[0][dd] * wk;
            q1 += sm->g.bufB[1][dd] * wk;
        }
        part[(0*2+h)*D + e] = q0;
        part[(1*2+h)*D + e] = q1;
        __syncthreads();
        g_qt[(row0 + h)*D + e] = part[(h*2+0)*D + e] + part[(h*2+1)*D + e];
    }
}

// ---------------- attn phase: all 128 blocks, 128 tokens each ----------------
__device__ void attn_phase(SU* sm, int blk, int t,
    const float* __restrict__ x, int f,
    const float* __restrict__ g_in, const float* __restrict__ be_in,
    float* __restrict__ out_attn, int warm)
{
    int b = blk >> 3, jc = blk & 7;
    int w = t >> 5, lane = t & 31;

    for (int i = t; i < S*D; i += THR) sm->a.qts[i] = g_qt[b*S*D + i];
    if (t < D){ sm->a.sg[t] = g_in[t]; sm->a.sb[t] = be_in[t]; }
    if (t < S)  sm->a.qbs[t] = g_qb[b*S + t];
    __syncthreads();

    const float* xb = x + ((size_t)(b*NFR + f)) * NN * D;
    float* ao   = warm ? g_attn_warm : out_attn;
    size_t base = warm ? (size_t)b * (S*NN)
                       : ((size_t)(b*NFR + f)) * (S*NN);

    int e0 = lane*4;
    float w0 = sm->a.sg[e0], w1 = sm->a.sg[e0+1], w2 = sm->a.sg[e0+2], w3 = sm->a.sg[e0+3];
    float c0 = sm->a.sb[e0], c1 = sm->a.sb[e0+1], c2 = sm->a.sb[e0+2], c3 = sm->a.sb[e0+3];

    float acc[32];
    #pragma unroll
    for (int i = 0; i < 32; i++) acc[i] = 0.0f;
    float rsl = 0.0f;

    int jwarp = jc*128 + w*16;
    #pragma unroll
    for (int p = 0; p < 4; p++){
        float4 xv4[4];
        #pragma unroll
        for (int q = 0; q < 4; q++)
            xv4[q] = *(const float4*)(xb + (size_t)(jwarp + p*4 + q)*D + e0);
        #pragma unroll
        for (int q = 0; q < 4; q++){
            int j = jwarp + p*4 + q;
            float4 xv = xv4[q];
            float smn = wred(xv.x + xv.y + xv.z + xv.w);
            float mean = smn * (1.0f/D);
            float d0 = xv.x-mean, d1 = xv.y-mean, d2 = xv.z-mean, d3 = xv.w-mean;
            float vs = wred(d0*d0 + d1*d1 + d2*d2 + d3*d3);
            float rstd = rsqrtf(vs * (1.0f/D) + 1e-5f);
            float l0 = d0*rstd*w0 + c0;
            float l1 = d1*rstd*w1 + c1;
            float l2v = d2*rstd*w2 + c2;
            float l3 = d3*rstd*w3 + c3;

            float dots[S];
            #pragma unroll
            for (int s = 0; s < S; s++){
                const float* qr = &sm->a.qts[s*D + e0];
                float p_ = l0*qr[0] + l1*qr[1] + l2v*qr[2] + l3*qr[3];
                p_ = wred(p_);
                dots[s] = (p_ + sm->a.qbs[s]) * SCL;
            }
            float mx = dots[0];
            #pragma unroll
            for (int s = 1; s < S; s++) mx = fmaxf(mx, dots[s]);
            float ssum = 0.0f;
            #pragma unroll
            for (int s = 0; s < S; s++){ dots[s] = __expf(dots[s] - mx); ssum += dots[s]; }
            float inv = 1.0f / ssum;
            #pragma unroll
            for (int s = 0; s < S; s++){
                float p_ = dots[s] * inv + EPSA;
                if (lane == s){
                    ao[base + (size_t)s*NN + j] = p_;
                    rsl += p_;
                }
                acc[s*4+0] += p_ * l0;
                acc[s*4+1] += p_ * l1;
                acc[s*4+2] += p_ * l2v;
                acc[s*4+3] += p_ * l3;
            }
        }
    }

    // block reduction -> per-(b,jc) partials (no atomics)
    #pragma unroll
    for (int s = 0; s < S; s++)
        #pragma unroll
        for (int qd = 0; qd < 4; qd++)
            sm->a.swacc[((w*S + s)*4 + qd)*32 + lane] = acc[s*4 + qd];
    if (lane < 8) sm->a.srs[w][lane] = rsl;
    __syncthreads();

    for (int i = t; i < S*D; i += THR){
        int s = i >> 7, rem = i & 127, qd = rem >> 5, li = rem & 31;
        float v = 0.0f;
        #pragma unroll
        for (int ww = 0; ww < 8; ww++) v += sm->a.swacc[((ww*S + s)*4 + qd)*32 + li];
        g_upart[((b*8 + jc)*S + s)*D + (li*4 + qd)] = v;
    }
    if (t < 8){
        float v = 0.0f;
        #pragma unroll
        for (int ww = 0; ww < 8; ww++) v += sm->a.srs[ww][t];
        g_rspart[(b*8 + jc)*S + t] = v;
    }
}

// ---------------- the persistent kernel ----------------
__global__ __launch_bounds__(THR, 1)
void k_persist(const float* __restrict__ inputs, const float* __restrict__ slots_init,
               const float* __restrict__ Wq,  const float* __restrict__ bq,
               const float* __restrict__ Wk,  const float* __restrict__ bk,
               const float* __restrict__ Wv,  const float* __restrict__ bv,
               const float* __restrict__ W1,  const float* __restrict__ b1,
               const float* __restrict__ W2,  const float* __restrict__ b2,
               const float* __restrict__ Wih, const float* __restrict__ Whh,
               const float* __restrict__ bih, const float* __restrict__ bhh,
               const float* __restrict__ g_in, const float* __restrict__ be_in,
               const float* __restrict__ g_sl, const float* __restrict__ be_sl,
               const float* __restrict__ g_ff, const float* __restrict__ be_ff,
               float* __restrict__ out_slots, float* __restrict__ out_attn)
{
    __shared__ SU sm;
    int blk = blockIdx.x, t = threadIdx.x;

    // init slots
    {
        int i = blk*THR + t;
        if (i < BB*S*D) g_slots[i] = slots_init[i & (S*D - 1)];
    }
    gbar();

    // initial q projection from initial slots
    if (blk < 64)
        slot_update(&sm, blk, t, false,
                    Wv, bv, Wih, Whh, bih, bhh, g_ff, be_ff,
                    W1, b1, W2, b2, Wq, bq, Wk, bk, g_sl, be_sl,
                    out_slots, 0, 0);
    gbar();

    for (int it = 0; it <= NFR; it++){
        int f    = (it == 0) ? 0 : it - 1;
        int warm = (it == 0) ? 1 : 0;

        attn_phase(&sm, blk, t, inputs, f, g_in, be_in, out_attn, warm);
        gbar();

        if (blk < 64)
            slot_update(&sm, blk, t, true,
                        Wv, bv, Wih, Whh, bih, bhh, g_ff, be_ff,
                        W1, b1, W2, b2, Wq, bq, Wk, bk, g_sl, be_sl,
                        out_slots, f, warm ? 0 : 1);
        gbar();
    }
}

// ---------------- host ----------------
extern "C" void kernel_launch(void* const* d_in, const int* in_sizes, int n_in,
                              void* d_out, int out_size){
    const float* inputs     = (const float*)d_in[0];
    const float* slots_init = (const float*)d_in[1];
    const float* Wq  = (const float*)d_in[2];
    const float* bq  = (const float*)d_in[3];
    const float* Wk  = (const float*)d_in[4];
    const float* bk  = (const float*)d_in[5];
    const float* Wv  = (const float*)d_in[6];
    const float* bv  = (const float*)d_in[7];
    const float* W1  = (const float*)d_in[8];
    const float* b1  = (const float*)d_in[9];
    const float* W2  = (const float*)d_in[10];
    const float* b2  = (const float*)d_in[11];
    const float* Wih = (const float*)d_in[12];
    const float* Whh = (const float*)d_in[13];
    const float* bih = (const float*)d_in[14];
    const float* bhh = (const float*)d_in[15];
    const float* g_in  = (const float*)d_in[16];
    const float* be_in = (const float*)d_in[17];
    const float* g_sl  = (const float*)d_in[18];
    const float* be_sl = (const float*)d_in[19];
    const float* g_ff  = (const float*)d_in[20];
    const float* be_ff = (const float*)d_in[21];

    float* out       = (float*)d_out;
    float* out_slots = out;                         // [B, NF, S, D]
    float* out_attn  = out + (size_t)BB*NFR*S*D;    // [B, NF, S, N]

    k_persist<<<NBLK, THR>>>(inputs, slots_init,
                             Wq, bq, Wk, bk, Wv, bv, W1, b1, W2, b2,
                             Wih, Whh, bih, bhh,
                             g_in, be_in, g_sl, be_sl, g_ff, be_ff,
                             out_slots, out_attn);
}